// round 1
// baseline (speedup 1.0000x reference)
#include <cuda_runtime.h>

// Problem constants (fixed by the reference build)
#define Bn 4
#define Cn 32
#define Ln 256
#define Mn 256
#define Fn 8
#define Nw 64
#define FP (Fn/2)   // f-pairs for f32x2 packing

__device__ __forceinline__ unsigned long long pack2(float lo, float hi) {
    unsigned long long r;
    asm("mov.b64 %0, {%1, %2};" : "=l"(r) : "f"(lo), "f"(hi));
    return r;
}
__device__ __forceinline__ void ffma2(unsigned long long& d,
                                      unsigned long long a,
                                      unsigned long long b) {
    asm("fma.rn.f32x2 %0, %1, %2, %0;" : "+l"(d) : "l"(a), "l"(b));
}
__device__ __forceinline__ float2 unpack2(unsigned long long v) {
    float2 r;
    asm("mov.b64 {%0, %1}, %2;" : "=f"(r.x), "=f"(r.y) : "l"(v));
    return r;
}

__global__ __launch_bounds__(256, 6)
void sphereconv_kernel(const float* __restrict__ xr,
                       const float* __restrict__ xi,
                       const float* __restrict__ wr,
                       const float* __restrict__ wi,
                       float* __restrict__ out)
{
    // Packed weight tiles for this l: [FP][Cn] pairs (f even/odd interleaved)
    __shared__ __align__(16) float s_wr [FP * Cn * 2];
    __shared__ __align__(16) float s_wi [FP * Cn * 2];
    __shared__ __align__(16) float s_nwi[FP * Cn * 2];

    const int l = blockIdx.x;
    const int b = blockIdx.y;
    const int t = threadIdx.x;

    // ---- Phase 1: interpolate weights for this l into smem (F*C = 256 entries) ----
    {
        const int f = t >> 5;   // 0..7
        const int c = t & 31;   // 0..31
        // tfp interp_regular_1d_grid: t = l/(L-1) * (N-1), linear interp
        float tt = ((float)l / (float)(Ln - 1)) * (float)(Nw - 1);
        int lo = (int)floorf(tt);
        lo = lo < 0 ? 0 : (lo > Nw - 2 ? Nw - 2 : lo);
        float frac = tt - (float)lo;
        const int base = (f * Cn + c) * Nw;      // w shape (F, C, N, 1)
        float wre = wr[base + lo] * (1.0f - frac) + wr[base + lo + 1] * frac;
        float wim = wi[base + lo] * (1.0f - frac) + wi[base + lo + 1] * frac;
        const int fp = f >> 1, lane = f & 1;
        const int sidx = (fp * Cn + c) * 2 + lane;
        s_wr [sidx] = wre;
        s_wi [sidx] = wim;
        s_nwi[sidx] = -wim;     // pre-negated: f32x2 fma has no operand negation
    }
    __syncthreads();

    const unsigned long long* __restrict__ pwr  = (const unsigned long long*)s_wr;
    const unsigned long long* __restrict__ pwi  = (const unsigned long long*)s_wi;
    const unsigned long long* __restrict__ pnwi = (const unsigned long long*)s_nwi;

    // ---- Phase 2: thread t owns m = t; reduce over c ----
    const int m = t;
    const size_t strideC = (size_t)Ln * Mn;                       // 65536
    const size_t xbase   = (size_t)b * Cn * Ln * Mn + (size_t)l * Mn + m;
    const float* __restrict__ xrp = xr + xbase;
    const float* __restrict__ xip = xi + xbase;

    unsigned long long ar[FP], ai[FP];
    #pragma unroll
    for (int p = 0; p < FP; p++) { ar[p] = 0ULL; ai[p] = 0ULL; }

    #pragma unroll 8
    for (int c = 0; c < Cn; c++) {
        const float xrv = __ldg(xrp + (size_t)c * strideC);
        const float xiv = __ldg(xip + (size_t)c * strideC);
        const unsigned long long xr2 = pack2(xrv, xrv);
        const unsigned long long xi2 = pack2(xiv, xiv);
        #pragma unroll
        for (int p = 0; p < FP; p++) {
            const unsigned long long w_r  = pwr [p * Cn + c];   // LDS.64 broadcast
            const unsigned long long w_i  = pwi [p * Cn + c];
            const unsigned long long w_ni = pnwi[p * Cn + c];
            ffma2(ar[p], w_r,  xr2);   // +wr*xr
            ffma2(ar[p], w_ni, xi2);   // -wi*xi
            ffma2(ai[p], w_r,  xi2);   // +wr*xi
            ffma2(ai[p], w_i,  xr2);   // +wi*xr
        }
    }

    // ---- Phase 3: mean over C, scale by sqrt(1+l), relu on real part, store ----
    const float sc = sqrtf(1.0f + (float)l) * (1.0f / (float)Cn);
    const size_t lm      = (size_t)Ln * Mn;
    const size_t obase   = ((size_t)b * Fn * Ln + l) * Mn + m;    // f=0, part=0
    const size_t partOff = (size_t)Bn * Fn * Ln * Mn;

    #pragma unroll
    for (int p = 0; p < FP; p++) {
        const float2 r2 = unpack2(ar[p]);
        const float2 i2 = unpack2(ai[p]);
        const size_t o0 = obase + (size_t)(2 * p)     * lm;
        const size_t o1 = obase + (size_t)(2 * p + 1) * lm;
        out[o0]           = fmaxf(r2.x * sc, 0.0f);
        out[o1]           = fmaxf(r2.y * sc, 0.0f);
        out[o0 + partOff] = i2.x * sc;
        out[o1 + partOff] = i2.y * sc;
    }
}

extern "C" void kernel_launch(void* const* d_in, const int* in_sizes, int n_in,
                              void* d_out, int out_size) {
    const float* xr = (const float*)d_in[0];
    const float* xi = (const float*)d_in[1];
    const float* wr = (const float*)d_in[2];
    const float* wi = (const float*)d_in[3];
    float* out = (float*)d_out;

    dim3 grid(Ln, Bn);   // one CTA per (l, b)
    sphereconv_kernel<<<grid, 256>>>(xr, xi, wr, wi, out);
}

// round 2
// speedup vs baseline: 1.0021x; 1.0021x over previous
#include <cuda_runtime.h>

// Problem constants (fixed by the reference build)
#define Bn 4
#define Cn 32
#define Ln 256
#define Mn 256
#define Fn 8
#define Nw 64
#define FP (Fn/2)   // f-pairs for f32x2 packing

typedef unsigned long long u64;

__device__ __forceinline__ u64 pack2(float lo, float hi) {
    u64 r;
    asm("mov.b64 %0, {%1, %2};" : "=l"(r) : "f"(lo), "f"(hi));
    return r;
}
__device__ __forceinline__ void ffma2(u64& d, u64 a, u64 b) {
    asm("fma.rn.f32x2 %0, %1, %2, %0;" : "+l"(d) : "l"(a), "l"(b));
}
__device__ __forceinline__ float2 unpack2(u64 v) {
    float2 r;
    asm("mov.b64 {%0, %1}, %2;" : "=f"(r.x), "=f"(r.y) : "l"(v));
    return r;
}

// CTA: 128 threads. Covers (m-half [128], one l, a pair of b).
// Each thread: one m, 2 b, all 8 f (as 4 f32x2 f-pairs), reduced over c=32.
__global__ __launch_bounds__(128, 7)
void sphereconv_kernel(const float* __restrict__ xr,
                       const float* __restrict__ xi,
                       const float* __restrict__ wr,
                       const float* __restrict__ wi,
                       float* __restrict__ out)
{
    // Per (f-pair p, c): float4 {wr_{2p}, wr_{2p+1}, wi_{2p}, wi_{2p+1}}
    __shared__ __align__(16) float s_w[FP * Cn * 4];

    const int mh = blockIdx.x;          // 0..1 : which half of m
    const int l  = blockIdx.y;          // 0..255
    const int bp = blockIdx.z;          // 0..1 : which pair of b
    const int t  = threadIdx.x;         // 0..127
    const int m  = (mh << 7) + t;

    // ---- Phase 1: interpolate weights for this l (F*C = 256 entries, 2/thread) ----
    {
        float tt = ((float)l / (float)(Ln - 1)) * (float)(Nw - 1);
        int lo = (int)tt;                       // tt >= 0 so trunc == floor
        lo = lo > Nw - 2 ? Nw - 2 : lo;
        float frac = tt - (float)lo;
        #pragma unroll
        for (int e = t; e < Fn * Cn; e += 128) {
            int f = e >> 5, c = e & 31;
            int base = (f * Cn + c) * Nw;       // w shape (F, C, N, 1)
            float wre = wr[base + lo] * (1.0f - frac) + wr[base + lo + 1] * frac;
            float wim = wi[base + lo] * (1.0f - frac) + wi[base + lo + 1] * frac;
            int p = f >> 1, lane = f & 1;
            s_w[((p * Cn + c) << 2) + lane]     = wre;
            s_w[((p * Cn + c) << 2) + 2 + lane] = wim;
        }
    }
    __syncthreads();

    // ---- Phase 2: reduce over c for 2 b values ----
    const int b0 = bp << 1;
    const size_t strideC = (size_t)Ln * Mn;                 // 65536
    const size_t strideB = (size_t)Cn * strideC;
    const size_t xbase   = (size_t)b0 * strideB + (size_t)l * Mn + m;
    const float* __restrict__ xr0 = xr + xbase;
    const float* __restrict__ xi0 = xi + xbase;
    const float* __restrict__ xr1 = xr0 + strideB;
    const float* __restrict__ xi1 = xi0 + strideB;

    const ulonglong2* __restrict__ pw = (const ulonglong2*)s_w;

    u64 ar[2][FP], ai[2][FP];
    #pragma unroll
    for (int bb = 0; bb < 2; bb++)
        #pragma unroll
        for (int p = 0; p < FP; p++) { ar[bb][p] = 0ULL; ai[bb][p] = 0ULL; }

    #pragma unroll 4
    for (int c = 0; c < Cn; c++) {
        const size_t off = (size_t)c * strideC;
        // Batch all 4 global loads first (MLP)
        const float xr0v = __ldg(xr0 + off);
        const float xi0v = __ldg(xi0 + off);
        const float xr1v = __ldg(xr1 + off);
        const float xi1v = __ldg(xi1 + off);
        // 4x LDS.128: weight pairs for all f, shared across both b
        ulonglong2 ww[FP];
        #pragma unroll
        for (int p = 0; p < FP; p++) ww[p] = pw[p * Cn + c];  // .x = wr2, .y = wi2

        {   // b = b0
            const u64 xr2  = pack2(xr0v, xr0v);
            const u64 xi2  = pack2(xi0v, xi0v);
            const float nx = -xi0v;
            const u64 nxi2 = pack2(nx, nx);
            #pragma unroll
            for (int p = 0; p < FP; p++) {
                ffma2(ar[0][p], ww[p].x, xr2);    // +wr*xr
                ffma2(ar[0][p], ww[p].y, nxi2);   // -wi*xi
                ffma2(ai[0][p], ww[p].x, xi2);    // +wr*xi
                ffma2(ai[0][p], ww[p].y, xr2);    // +wi*xr
            }
        }
        {   // b = b0 + 1
            const u64 xr2  = pack2(xr1v, xr1v);
            const u64 xi2  = pack2(xi1v, xi1v);
            const float nx = -xi1v;
            const u64 nxi2 = pack2(nx, nx);
            #pragma unroll
            for (int p = 0; p < FP; p++) {
                ffma2(ar[1][p], ww[p].x, xr2);
                ffma2(ar[1][p], ww[p].y, nxi2);
                ffma2(ai[1][p], ww[p].x, xi2);
                ffma2(ai[1][p], ww[p].y, xr2);
            }
        }
    }

    // ---- Phase 3: mean over C, scale by sqrt(1+l), relu on real part, store ----
    const float sc = sqrtf(1.0f + (float)l) * (1.0f / (float)Cn);
    const size_t lm      = (size_t)Ln * Mn;
    const size_t partOff = (size_t)Bn * Fn * lm;

    #pragma unroll
    for (int bb = 0; bb < 2; bb++) {
        const size_t obase = (((size_t)(b0 + bb) * Fn * Ln) + l) * Mn + m; // f=0, real
        #pragma unroll
        for (int p = 0; p < FP; p++) {
            const float2 r2 = unpack2(ar[bb][p]);
            const float2 i2 = unpack2(ai[bb][p]);
            const size_t o0 = obase + (size_t)(2 * p)     * lm;
            const size_t o1 = obase + (size_t)(2 * p + 1) * lm;
            out[o0]           = fmaxf(r2.x * sc, 0.0f);
            out[o1]           = fmaxf(r2.y * sc, 0.0f);
            out[o0 + partOff] = i2.x * sc;
            out[o1 + partOff] = i2.y * sc;
        }
    }
}

extern "C" void kernel_launch(void* const* d_in, const int* in_sizes, int n_in,
                              void* d_out, int out_size) {
    const float* xr = (const float*)d_in[0];
    const float* xi = (const float*)d_in[1];
    const float* wr = (const float*)d_in[2];
    const float* wi = (const float*)d_in[3];
    float* out = (float*)d_out;

    dim3 grid(2, Ln, Bn / 2);   // (m-half, l, b-pair) = 1024 CTAs of 128 threads
    sphereconv_kernel<<<grid, 128>>>(xr, xi, wr, wi, out);
}

// round 5
// speedup vs baseline: 1.4803x; 1.4773x over previous
#include <cuda_runtime.h>

// Problem constants (fixed by the reference build)
#define Bn 4
#define Cn 32
#define Ln 256
#define Mn 256
#define Fn 8
#define Nw 64
#define FP (Fn/2)     // f-pairs for f32x2 packing
#define CH 4          // c's per register-pipeline chunk
#define NCH (Cn/CH)   // 8 chunks

typedef unsigned long long u64;

__device__ __forceinline__ u64 pack2(float lo, float hi) {
    u64 r;
    asm("mov.b64 %0, {%1, %2};" : "=l"(r) : "f"(lo), "f"(hi));
    return r;
}
__device__ __forceinline__ void ffma2(u64& d, u64 a, u64 b) {
    asm("fma.rn.f32x2 %0, %1, %2, %0;" : "+l"(d) : "l"(a), "l"(b));
}
__device__ __forceinline__ float2 unpack2(u64 v) {
    float2 r;
    asm("mov.b64 {%0, %1}, %2;" : "=f"(r.x), "=f"(r.y) : "l"(v));
    return r;
}

__global__ __launch_bounds__(256, 3)
void sphereconv_kernel(const float* __restrict__ xr,
                       const float* __restrict__ xi,
                       const float* __restrict__ wr,
                       const float* __restrict__ wi,
                       float* __restrict__ out)
{
    // Per (f-pair p, c): float4 {wr_{2p}, wr_{2p+1}, wi_{2p}, wi_{2p+1}}  (2 KB)
    __shared__ __align__(16) float s_w[FP * Cn * 4];

    const int l = blockIdx.x;           // 0..255
    const int b = blockIdx.y;           // 0..3
    const int t = threadIdx.x;          // 0..255 (== m)

    // ---- Phase 1: interpolate weights for this l (F*C = 256, one per thread) ----
    {
        float tt = ((float)l / (float)(Ln - 1)) * (float)(Nw - 1);
        int lo = (int)tt;                       // tt >= 0 -> trunc == floor
        lo = lo > Nw - 2 ? Nw - 2 : lo;
        float frac = tt - (float)lo;
        int f = t >> 5, c = t & 31;
        int base = (f * Cn + c) * Nw;           // w shape (F, C, N, 1)
        float wre = wr[base + lo] * (1.0f - frac) + wr[base + lo + 1] * frac;
        float wim = wi[base + lo] * (1.0f - frac) + wi[base + lo + 1] * frac;
        int p = f >> 1, lane = f & 1;
        s_w[((p * Cn + c) << 2) + lane]     = wre;
        s_w[((p * Cn + c) << 2) + 2 + lane] = wim;
    }
    __syncthreads();

    const ulonglong2* __restrict__ pw = (const ulonglong2*)s_w;

    const size_t strideC = (size_t)Ln * Mn;                         // 65536
    const size_t xbase   = (size_t)b * Cn * strideC + (size_t)l * Mn + t;
    const float* __restrict__ xrp = xr + xbase;
    const float* __restrict__ xip = xi + xbase;

    u64 ar[FP], ai[FP];
    #pragma unroll
    for (int p = 0; p < FP; p++) { ar[p] = 0ULL; ai[p] = 0ULL; }

    // Register double buffer: x values for one chunk of CH c's
    float bR[2][CH], bI[2][CH];

    // Prologue: load chunk 0 (8 batched LDGs -> MLP 8)
    #pragma unroll
    for (int j = 0; j < CH; j++) bR[0][j] = __ldg(xrp + (size_t)j * strideC);
    #pragma unroll
    for (int j = 0; j < CH; j++) bI[0][j] = __ldg(xip + (size_t)j * strideC);

    #pragma unroll
    for (int k = 0; k < NCH; k++) {
        const int cur = k & 1, nxt = cur ^ 1;

        // Prefetch chunk k+1 into the other buffer BEFORE computing chunk k
        if (k + 1 < NCH) {
            const size_t off = (size_t)((k + 1) * CH) * strideC;
            #pragma unroll
            for (int j = 0; j < CH; j++) bR[nxt][j] = __ldg(xrp + off + (size_t)j * strideC);
            #pragma unroll
            for (int j = 0; j < CH; j++) bI[nxt][j] = __ldg(xip + off + (size_t)j * strideC);
        }

        // Compute chunk k from registers
        #pragma unroll
        for (int j = 0; j < CH; j++) {
            const int c = k * CH + j;
            const float xrv = bR[cur][j];
            const float xiv = bI[cur][j];
            const u64 xr2  = pack2(xrv, xrv);
            const u64 xi2  = pack2(xiv, xiv);
            const float nx = -xiv;
            const u64 nxi2 = pack2(nx, nx);

            ulonglong2 ww[FP];
            #pragma unroll
            for (int p = 0; p < FP; p++) ww[p] = pw[p * Cn + c];  // LDS.128 broadcast

            #pragma unroll
            for (int p = 0; p < FP; p++) {
                ffma2(ar[p], ww[p].x, xr2);    // +wr*xr
                ffma2(ar[p], ww[p].y, nxi2);   // -wi*xi
                ffma2(ai[p], ww[p].x, xi2);    // +wr*xi
                ffma2(ai[p], ww[p].y, xr2);    // +wi*xr
            }
        }
    }

    // ---- Epilogue: mean over C, scale sqrt(1+l), relu real part, store ----
    const float sc = sqrtf(1.0f + (float)l) * (1.0f / (float)Cn);
    const size_t lm      = (size_t)Ln * Mn;
    const size_t partOff = (size_t)Bn * Fn * lm;
    const size_t obase   = (((size_t)b * Fn * Ln) + l) * Mn + t;   // f=0, real part

    #pragma unroll
    for (int p = 0; p < FP; p++) {
        const float2 r2 = unpack2(ar[p]);
        const float2 i2 = unpack2(ai[p]);
        const size_t o0 = obase + (size_t)(2 * p)     * lm;
        const size_t o1 = obase + (size_t)(2 * p + 1) * lm;
        out[o0]           = fmaxf(r2.x * sc, 0.0f);
        out[o1]           = fmaxf(r2.y * sc, 0.0f);
        out[o0 + partOff] = i2.x * sc;
        out[o1 + partOff] = i2.y * sc;
    }
}

extern "C" void kernel_launch(void* const* d_in, const int* in_sizes, int n_in,
                              void* d_out, int out_size) {
    const float* xr = (const float*)d_in[0];
    const float* xi = (const float*)d_in[1];
    const float* wr = (const float*)d_in[2];
    const float* wi = (const float*)d_in[3];
    float* out = (float*)d_out;

    dim3 grid(Ln, Bn);   // (l, b) = 1024 CTAs of 256 threads
    sphereconv_kernel<<<grid, 256>>>(xr, xi, wr, wi, out);
}